// round 13
// baseline (speedup 1.0000x reference)
#include <cuda_runtime.h>
#include <cuda_fp16.h>

#define B_    32
#define NIN   2048
#define DIN   16
#define J_    64
#define C_    32
#define ITERS 5
#define EPS_  1e-7f

#define RT    512        // routing threads per CTA (4 rows/thread)

#define FMA_F32X2(d, a, b, c) \
    asm("fma.rn.f32x2 %0, %1, %2, %3;" : "=l"(d) : "l"(a), "l"(b), "l"(c))

// u_hat fp16, layout [b][j][i][c]  (256 MB scratch)
__device__ __half g_uhat[(size_t)B_ * J_ * NIN * C_];

__device__ __forceinline__ __half2 u2h2(unsigned x) { return *(__half2*)&x; }

// ---------------------------------------------------------------------------
// Stage 1: u_hat[b,j,i,c] = sum_d W[i,j,c,d] * x[b,i,d].  One block per i.
// R6 shape (256 thr, thread = 1 j x 4 c, STG.64) + b-PAIR interleaving:
// two independent up/acc register streams hide LDS latency under FMAs.
// ---------------------------------------------------------------------------
__global__ void __launch_bounds__(256, 2) uhat_kernel(const float* __restrict__ x,
                                                      const float* __restrict__ W)
{
    __shared__ float4 us4[B_][DIN / 4];
    const int i   = blockIdx.x;
    const int tid = threadIdx.x;

    for (int t = tid; t < B_ * DIN; t += 256) {
        int b = t / DIN, d = t % DIN;
        ((float*)us4)[t] = x[((size_t)b * NIN + i) * DIN + d];
    }
    __syncthreads();

    const int warp = tid >> 5;
    const int lane = tid & 31;
    const int c4   = lane & 7;          // c block: 4*c4 .. 4*c4+3
    const int jq   = lane >> 3;         // 0..3

    #pragma unroll
    for (int jo = 0; jo < 2; jo++) {
        const int j = warp * 8 + jo * 4 + jq;
        unsigned long long wq[4][8];
        #pragma unroll
        for (int rr = 0; rr < 4; rr++) {
            const ulonglong2* wp =
                (const ulonglong2*)(W + (((size_t)i * J_ + j) * C_ + 4 * c4 + rr) * DIN);
            #pragma unroll
            for (int q2 = 0; q2 < 4; q2++) {
                ulonglong2 v = wp[q2];
                wq[rr][q2 * 2] = v.x;  wq[rr][q2 * 2 + 1] = v.y;
            }
        }
        #pragma unroll 2
        for (int b = 0; b < B_; b += 2) {
            // two independent streams: b and b+1
            unsigned long long upA[8], upB[8];
            {
                const ulonglong2* uA = (const ulonglong2*)&us4[b][0];
                const ulonglong2* uB = (const ulonglong2*)&us4[b + 1][0];
                #pragma unroll
                for (int q2 = 0; q2 < 4; q2++) {
                    ulonglong2 va = uA[q2];
                    upA[q2 * 2] = va.x;  upA[q2 * 2 + 1] = va.y;
                }
                #pragma unroll
                for (int q2 = 0; q2 < 4; q2++) {
                    ulonglong2 vb = uB[q2];
                    upB[q2 * 2] = vb.x;  upB[q2 * 2 + 1] = vb.y;
                }
            }
            unsigned long long accA[4] = {0ull, 0ull, 0ull, 0ull};
            unsigned long long accB[4] = {0ull, 0ull, 0ull, 0ull};
            #pragma unroll
            for (int q = 0; q < 8; q++) {
                FMA_F32X2(accA[0], wq[0][q], upA[q], accA[0]);
                FMA_F32X2(accB[0], wq[0][q], upB[q], accB[0]);
                FMA_F32X2(accA[1], wq[1][q], upA[q], accA[1]);
                FMA_F32X2(accB[1], wq[1][q], upB[q], accB[1]);
                FMA_F32X2(accA[2], wq[2][q], upA[q], accA[2]);
                FMA_F32X2(accB[2], wq[2][q], upB[q], accB[2]);
                FMA_F32X2(accA[3], wq[3][q], upA[q], accA[3]);
                FMA_F32X2(accB[3], wq[3][q], upB[q], accB[3]);
            }
            {
                float2 f0 = *(float2*)&accA[0], f1 = *(float2*)&accA[1];
                float2 f2 = *(float2*)&accA[2], f3 = *(float2*)&accA[3];
                __half2 h01 = __floats2half2_rn(f0.x + f0.y, f1.x + f1.y);
                __half2 h23 = __floats2half2_rn(f2.x + f2.y, f3.x + f3.y);
                uint2 st = make_uint2(*(unsigned*)&h01, *(unsigned*)&h23);
                *(uint2*)(g_uhat + (((size_t)b * J_ + j) * NIN + i) * C_ + 4 * c4) = st;
            }
            {
                float2 f0 = *(float2*)&accB[0], f1 = *(float2*)&accB[1];
                float2 f2 = *(float2*)&accB[2], f3 = *(float2*)&accB[3];
                __half2 h01 = __floats2half2_rn(f0.x + f0.y, f1.x + f1.y);
                __half2 h23 = __floats2half2_rn(f2.x + f2.y, f3.x + f3.y);
                uint2 st = make_uint2(*(unsigned*)&h01, *(unsigned*)&h23);
                *(uint2*)(g_uhat + (((size_t)(b + 1) * J_ + j) * NIN + i) * C_ + 4 * c4) = st;
            }
        }
    }
}

// ---------------------------------------------------------------------------
// Stage 2: routing (measured 154.8 us config — unchanged). One CTA per (b,j),
// 512 threads, 4 rows/thread in registers; fused dot + b-update + exp +
// weighted s-accumulation; reductions via SMEM.
// ---------------------------------------------------------------------------
__global__ void __launch_bounds__(RT) routing_kernel(float* __restrict__ out)
{
    __shared__ __half2 part[RT][20];
    __shared__ float  part3[32][33];
    __shared__ float  redz[16], redm[16];
    __shared__ __half2 v2_sh[C_ / 2];
    __shared__ float  Msh;

    const int tid  = threadIdx.x;
    const int warp = tid >> 5, lane = tid & 31;
    const int bj   = blockIdx.x;

    uint4   row[4][4];
    __half2 s_acc[16];
    #pragma unroll
    for (int t = 0; t < 16; t++) s_acc[t] = __half2half2(__ushort_as_half(0));
    {
        const uint4* src = (const uint4*)(g_uhat + (size_t)bj * (NIN * C_));
        #pragma unroll
        for (int k = 0; k < 4; k++) {
            #pragma unroll
            for (int c = 0; c < 4; c++) {
                uint4 q = src[(tid + k * RT) * 4 + c];
                row[k][c] = q;
                s_acc[c * 4 + 0] = __hadd2(s_acc[c * 4 + 0], u2h2(q.x));
                s_acc[c * 4 + 1] = __hadd2(s_acc[c * 4 + 1], u2h2(q.y));
                s_acc[c * 4 + 2] = __hadd2(s_acc[c * 4 + 2], u2h2(q.z));
                s_acc[c * 4 + 3] = __hadd2(s_acc[c * 4 + 3], u2h2(q.w));
            }
        }
    }

    float b[4] = {0.f, 0.f, 0.f, 0.f};
    float z = (float)NIN;
    float mloc = 0.f;

    for (int it = 0; it < ITERS; it++) {
        #pragma unroll
        for (int c = 0; c < 4; c++) {
            uint4 q;
            q.x = *(unsigned*)&s_acc[c * 4 + 0];
            q.y = *(unsigned*)&s_acc[c * 4 + 1];
            q.z = *(unsigned*)&s_acc[c * 4 + 2];
            q.w = *(unsigned*)&s_acc[c * 4 + 3];
            *(uint4*)&part[tid][c * 4] = q;
        }
        if (it > 0) {
            #pragma unroll
            for (int o = 16; o > 0; o >>= 1) {
                z    += __shfl_xor_sync(~0u, z, o);
                mloc  = fmaxf(mloc, __shfl_xor_sync(~0u, mloc, o));
            }
            if (lane == 0) { redz[warp] = z; redm[warp] = mloc; }
        }
        __syncthreads();

        {
            const int p = tid & 15, g = tid >> 4;
            __half2 a0 = part[g * 16 + 0][p];
            __half2 a1 = part[g * 16 + 8][p];
            #pragma unroll
            for (int q = 1; q < 8; q++) {
                a0 = __hadd2(a0, part[g * 16 + q][p]);
                a1 = __hadd2(a1, part[g * 16 + 8 + q][p]);
            }
            float2 F0 = __half22float2(a0), F1 = __half22float2(a1);
            part3[g][2 * p]     = F0.x + F1.x;
            part3[g][2 * p + 1] = F0.y + F1.y;
        }
        __syncthreads();

        if (tid < 32) {
            float s0 = part3[0][tid], s1 = part3[1][tid];
            float s2 = part3[2][tid], s3 = part3[3][tid];
            #pragma unroll
            for (int g = 4; g < 32; g += 4) {
                s0 += part3[g + 0][tid];
                s1 += part3[g + 1][tid];
                s2 += part3[g + 2][tid];
                s3 += part3[g + 3][tid];
            }
            float s = (s0 + s1) + (s2 + s3);
            float Z, M;
            if (it == 0) { Z = (float)NIN; M = 0.f; }
            else {
                float z0 = redz[0], z1 = redz[1];
                float m0 = redm[0], m1 = redm[1];
                #pragma unroll
                for (int w = 2; w < 16; w += 2) {
                    z0 += redz[w]; z1 += redz[w + 1];
                    m0 = fmaxf(m0, redm[w]); m1 = fmaxf(m1, redm[w + 1]);
                }
                Z = z0 + z1; M = fmaxf(m0, m1);
            }
            float sv = s / Z + EPS_;
            float n = sv * sv;
            #pragma unroll
            for (int o = 16; o > 0; o >>= 1) n += __shfl_xor_sync(~0u, n, o);
            float v = sv * (n / (1.f + n) * rsqrtf(n));
            if (it == ITERS - 1) {
                out[(size_t)bj * C_ + tid] = v;
            } else {
                float va = __shfl_sync(~0u, v, 2 * lane);
                float vb = __shfl_sync(~0u, v, 2 * lane + 1);
                if (lane < 16) v2_sh[lane] = __floats2half2_rn(va, vb);
                if (lane == 0) Msh = M;
            }
        }
        __syncthreads();
        if (it == ITERS - 1) return;

        __half2 vh[16];
        {
            const uint4* vv = (const uint4*)v2_sh;
            #pragma unroll
            for (int t = 0; t < 4; t++) {
                uint4 q = vv[t];
                vh[t * 4 + 0] = u2h2(q.x); vh[t * 4 + 1] = u2h2(q.y);
                vh[t * 4 + 2] = u2h2(q.z); vh[t * 4 + 3] = u2h2(q.w);
            }
        }
        const float Mprev = Msh;
        z = 0.f; mloc = -1e30f;
        #pragma unroll
        for (int t = 0; t < 16; t++) s_acc[t] = __half2half2(__ushort_as_half(0));

        #pragma unroll
        for (int k = 0; k < 4; k++) {
            __half2 a0 = __hmul2(vh[0],  u2h2(row[k][0].x));
            __half2 a1 = __hmul2(vh[4],  u2h2(row[k][1].x));
            __half2 a2 = __hmul2(vh[8],  u2h2(row[k][2].x));
            __half2 a3 = __hmul2(vh[12], u2h2(row[k][3].x));
            a0 = __hfma2(vh[1],  u2h2(row[k][0].y), a0);
            a1 = __hfma2(vh[5],  u2h2(row[k][1].y), a1);
            a2 = __hfma2(vh[9],  u2h2(row[k][2].y), a2);
            a3 = __hfma2(vh[13], u2h2(row[k][3].y), a3);
            a0 = __hfma2(vh[2],  u2h2(row[k][0].z), a0);
            a1 = __hfma2(vh[6],  u2h2(row[k][1].z), a1);
            a2 = __hfma2(vh[10], u2h2(row[k][2].z), a2);
            a3 = __hfma2(vh[14], u2h2(row[k][3].z), a3);
            a0 = __hfma2(vh[3],  u2h2(row[k][0].w), a0);
            a1 = __hfma2(vh[7],  u2h2(row[k][1].w), a1);
            a2 = __hfma2(vh[11], u2h2(row[k][2].w), a2);
            a3 = __hfma2(vh[15], u2h2(row[k][3].w), a3);
            float2 f0 = __half22float2(a0), f1 = __half22float2(a1);
            float2 f2 = __half22float2(a2), f3 = __half22float2(a3);
            float d = ((f0.x + f0.y) + (f1.x + f1.y)) + ((f2.x + f2.y) + (f3.x + f3.y));
            b[k] += d;
            float e = __expf(b[k] - Mprev);
            z += e;
            mloc = fmaxf(mloc, b[k]);
            __half2 eh = __half2half2(__float2half_rn(e));
            #pragma unroll
            for (int c = 0; c < 4; c++) {
                s_acc[c * 4 + 0] = __hfma2(eh, u2h2(row[k][c].x), s_acc[c * 4 + 0]);
                s_acc[c * 4 + 1] = __hfma2(eh, u2h2(row[k][c].y), s_acc[c * 4 + 1]);
                s_acc[c * 4 + 2] = __hfma2(eh, u2h2(row[k][c].z), s_acc[c * 4 + 2]);
                s_acc[c * 4 + 3] = __hfma2(eh, u2h2(row[k][c].w), s_acc[c * 4 + 3]);
            }
        }
    }
}

// ---------------------------------------------------------------------------
extern "C" void kernel_launch(void* const* d_in, const int* in_sizes, int n_in,
                              void* d_out, int out_size)
{
    const float* x = (const float*)d_in[0];
    const float* W = (const float*)d_in[1];
    if (n_in >= 2 && in_sizes[0] > in_sizes[1]) {
        x = (const float*)d_in[1];
        W = (const float*)d_in[0];
    }

    uhat_kernel<<<NIN, 256>>>(x, W);
    routing_kernel<<<B_ * J_, RT>>>((float*)d_out);

    (void)out_size;
}

// round 14
// speedup vs baseline: 1.0024x; 1.0024x over previous
#include <cuda_runtime.h>
#include <cuda_fp16.h>

#define B_    32
#define NIN   2048
#define DIN   16
#define J_    64
#define C_    32
#define ITERS 5
#define EPS_  1e-7f

#define RT    512        // routing threads per CTA (4 rows/thread)

#define FMA_F32X2(d, a, b, c) \
    asm("fma.rn.f32x2 %0, %1, %2, %3;" : "=l"(d) : "l"(a), "l"(b), "l"(c))

// u_hat fp16, layout [b][j][i][c]  (256 MB scratch)
__device__ __half g_uhat[(size_t)B_ * J_ * NIN * C_];

__device__ __forceinline__ __half2 u2h2(unsigned x) { return *(__half2*)&x; }

// ---------------------------------------------------------------------------
// Stage 1: u_hat[b,j,i,c] = sum_d W[i,j,c,d] * x[b,i,d].  One block per i.
// R6 shape (256 thr, thread = 1 j x 4 c, STG.64) + b-PAIR interleaving:
// two independent up/acc register streams hide LDS latency under FMAs.
// ---------------------------------------------------------------------------
__global__ void __launch_bounds__(256, 2) uhat_kernel(const float* __restrict__ x,
                                                      const float* __restrict__ W)
{
    __shared__ float4 us4[B_][DIN / 4];
    const int i   = blockIdx.x;
    const int tid = threadIdx.x;

    for (int t = tid; t < B_ * DIN; t += 256) {
        int b = t / DIN, d = t % DIN;
        ((float*)us4)[t] = x[((size_t)b * NIN + i) * DIN + d];
    }
    __syncthreads();

    const int warp = tid >> 5;
    const int lane = tid & 31;
    const int c4   = lane & 7;          // c block: 4*c4 .. 4*c4+3
    const int jq   = lane >> 3;         // 0..3

    #pragma unroll
    for (int jo = 0; jo < 2; jo++) {
        const int j = warp * 8 + jo * 4 + jq;
        unsigned long long wq[4][8];
        #pragma unroll
        for (int rr = 0; rr < 4; rr++) {
            const ulonglong2* wp =
                (const ulonglong2*)(W + (((size_t)i * J_ + j) * C_ + 4 * c4 + rr) * DIN);
            #pragma unroll
            for (int q2 = 0; q2 < 4; q2++) {
                ulonglong2 v = wp[q2];
                wq[rr][q2 * 2] = v.x;  wq[rr][q2 * 2 + 1] = v.y;
            }
        }
        #pragma unroll 2
        for (int b = 0; b < B_; b += 2) {
            // two independent streams: b and b+1
            unsigned long long upA[8], upB[8];
            {
                const ulonglong2* uA = (const ulonglong2*)&us4[b][0];
                const ulonglong2* uB = (const ulonglong2*)&us4[b + 1][0];
                #pragma unroll
                for (int q2 = 0; q2 < 4; q2++) {
                    ulonglong2 va = uA[q2];
                    upA[q2 * 2] = va.x;  upA[q2 * 2 + 1] = va.y;
                }
                #pragma unroll
                for (int q2 = 0; q2 < 4; q2++) {
                    ulonglong2 vb = uB[q2];
                    upB[q2 * 2] = vb.x;  upB[q2 * 2 + 1] = vb.y;
                }
            }
            unsigned long long accA[4] = {0ull, 0ull, 0ull, 0ull};
            unsigned long long accB[4] = {0ull, 0ull, 0ull, 0ull};
            #pragma unroll
            for (int q = 0; q < 8; q++) {
                FMA_F32X2(accA[0], wq[0][q], upA[q], accA[0]);
                FMA_F32X2(accB[0], wq[0][q], upB[q], accB[0]);
                FMA_F32X2(accA[1], wq[1][q], upA[q], accA[1]);
                FMA_F32X2(accB[1], wq[1][q], upB[q], accB[1]);
                FMA_F32X2(accA[2], wq[2][q], upA[q], accA[2]);
                FMA_F32X2(accB[2], wq[2][q], upB[q], accB[2]);
                FMA_F32X2(accA[3], wq[3][q], upA[q], accA[3]);
                FMA_F32X2(accB[3], wq[3][q], upB[q], accB[3]);
            }
            {
                float2 f0 = *(float2*)&accA[0], f1 = *(float2*)&accA[1];
                float2 f2 = *(float2*)&accA[2], f3 = *(float2*)&accA[3];
                __half2 h01 = __floats2half2_rn(f0.x + f0.y, f1.x + f1.y);
                __half2 h23 = __floats2half2_rn(f2.x + f2.y, f3.x + f3.y);
                uint2 st = make_uint2(*(unsigned*)&h01, *(unsigned*)&h23);
                *(uint2*)(g_uhat + (((size_t)b * J_ + j) * NIN + i) * C_ + 4 * c4) = st;
            }
            {
                float2 f0 = *(float2*)&accB[0], f1 = *(float2*)&accB[1];
                float2 f2 = *(float2*)&accB[2], f3 = *(float2*)&accB[3];
                __half2 h01 = __floats2half2_rn(f0.x + f0.y, f1.x + f1.y);
                __half2 h23 = __floats2half2_rn(f2.x + f2.y, f3.x + f3.y);
                uint2 st = make_uint2(*(unsigned*)&h01, *(unsigned*)&h23);
                *(uint2*)(g_uhat + (((size_t)(b + 1) * J_ + j) * NIN + i) * C_ + 4 * c4) = st;
            }
        }
    }
}

// ---------------------------------------------------------------------------
// Stage 2: routing (measured 154.8 us config — unchanged). One CTA per (b,j),
// 512 threads, 4 rows/thread in registers; fused dot + b-update + exp +
// weighted s-accumulation; reductions via SMEM.
// ---------------------------------------------------------------------------
__global__ void __launch_bounds__(RT) routing_kernel(float* __restrict__ out)
{
    __shared__ __half2 part[RT][20];
    __shared__ float  part3[32][33];
    __shared__ float  redz[16], redm[16];
    __shared__ __half2 v2_sh[C_ / 2];
    __shared__ float  Msh;

    const int tid  = threadIdx.x;
    const int warp = tid >> 5, lane = tid & 31;
    const int bj   = blockIdx.x;

    uint4   row[4][4];
    __half2 s_acc[16];
    #pragma unroll
    for (int t = 0; t < 16; t++) s_acc[t] = __half2half2(__ushort_as_half(0));
    {
        const uint4* src = (const uint4*)(g_uhat + (size_t)bj * (NIN * C_));
        #pragma unroll
        for (int k = 0; k < 4; k++) {
            #pragma unroll
            for (int c = 0; c < 4; c++) {
                uint4 q = src[(tid + k * RT) * 4 + c];
                row[k][c] = q;
                s_acc[c * 4 + 0] = __hadd2(s_acc[c * 4 + 0], u2h2(q.x));
                s_acc[c * 4 + 1] = __hadd2(s_acc[c * 4 + 1], u2h2(q.y));
                s_acc[c * 4 + 2] = __hadd2(s_acc[c * 4 + 2], u2h2(q.z));
                s_acc[c * 4 + 3] = __hadd2(s_acc[c * 4 + 3], u2h2(q.w));
            }
        }
    }

    float b[4] = {0.f, 0.f, 0.f, 0.f};
    float z = (float)NIN;
    float mloc = 0.f;

    for (int it = 0; it < ITERS; it++) {
        #pragma unroll
        for (int c = 0; c < 4; c++) {
            uint4 q;
            q.x = *(unsigned*)&s_acc[c * 4 + 0];
            q.y = *(unsigned*)&s_acc[c * 4 + 1];
            q.z = *(unsigned*)&s_acc[c * 4 + 2];
            q.w = *(unsigned*)&s_acc[c * 4 + 3];
            *(uint4*)&part[tid][c * 4] = q;
        }
        if (it > 0) {
            #pragma unroll
            for (int o = 16; o > 0; o >>= 1) {
                z    += __shfl_xor_sync(~0u, z, o);
                mloc  = fmaxf(mloc, __shfl_xor_sync(~0u, mloc, o));
            }
            if (lane == 0) { redz[warp] = z; redm[warp] = mloc; }
        }
        __syncthreads();

        {
            const int p = tid & 15, g = tid >> 4;
            __half2 a0 = part[g * 16 + 0][p];
            __half2 a1 = part[g * 16 + 8][p];
            #pragma unroll
            for (int q = 1; q < 8; q++) {
                a0 = __hadd2(a0, part[g * 16 + q][p]);
                a1 = __hadd2(a1, part[g * 16 + 8 + q][p]);
            }
            float2 F0 = __half22float2(a0), F1 = __half22float2(a1);
            part3[g][2 * p]     = F0.x + F1.x;
            part3[g][2 * p + 1] = F0.y + F1.y;
        }
        __syncthreads();

        if (tid < 32) {
            float s0 = part3[0][tid], s1 = part3[1][tid];
            float s2 = part3[2][tid], s3 = part3[3][tid];
            #pragma unroll
            for (int g = 4; g < 32; g += 4) {
                s0 += part3[g + 0][tid];
                s1 += part3[g + 1][tid];
                s2 += part3[g + 2][tid];
                s3 += part3[g + 3][tid];
            }
            float s = (s0 + s1) + (s2 + s3);
            float Z, M;
            if (it == 0) { Z = (float)NIN; M = 0.f; }
            else {
                float z0 = redz[0], z1 = redz[1];
                float m0 = redm[0], m1 = redm[1];
                #pragma unroll
                for (int w = 2; w < 16; w += 2) {
                    z0 += redz[w]; z1 += redz[w + 1];
                    m0 = fmaxf(m0, redm[w]); m1 = fmaxf(m1, redm[w + 1]);
                }
                Z = z0 + z1; M = fmaxf(m0, m1);
            }
            float sv = s / Z + EPS_;
            float n = sv * sv;
            #pragma unroll
            for (int o = 16; o > 0; o >>= 1) n += __shfl_xor_sync(~0u, n, o);
            float v = sv * (n / (1.f + n) * rsqrtf(n));
            if (it == ITERS - 1) {
                out[(size_t)bj * C_ + tid] = v;
            } else {
                float va = __shfl_sync(~0u, v, 2 * lane);
                float vb = __shfl_sync(~0u, v, 2 * lane + 1);
                if (lane < 16) v2_sh[lane] = __floats2half2_rn(va, vb);
                if (lane == 0) Msh = M;
            }
        }
        __syncthreads();
        if (it == ITERS - 1) return;

        __half2 vh[16];
        {
            const uint4* vv = (const uint4*)v2_sh;
            #pragma unroll
            for (int t = 0; t < 4; t++) {
                uint4 q = vv[t];
                vh[t * 4 + 0] = u2h2(q.x); vh[t * 4 + 1] = u2h2(q.y);
                vh[t * 4 + 2] = u2h2(q.z); vh[t * 4 + 3] = u2h2(q.w);
            }
        }
        const float Mprev = Msh;
        z = 0.f; mloc = -1e30f;
        #pragma unroll
        for (int t = 0; t < 16; t++) s_acc[t] = __half2half2(__ushort_as_half(0));

        #pragma unroll
        for (int k = 0; k < 4; k++) {
            __half2 a0 = __hmul2(vh[0],  u2h2(row[k][0].x));
            __half2 a1 = __hmul2(vh[4],  u2h2(row[k][1].x));
            __half2 a2 = __hmul2(vh[8],  u2h2(row[k][2].x));
            __half2 a3 = __hmul2(vh[12], u2h2(row[k][3].x));
            a0 = __hfma2(vh[1],  u2h2(row[k][0].y), a0);
            a1 = __hfma2(vh[5],  u2h2(row[k][1].y), a1);
            a2 = __hfma2(vh[9],  u2h2(row[k][2].y), a2);
            a3 = __hfma2(vh[13], u2h2(row[k][3].y), a3);
            a0 = __hfma2(vh[2],  u2h2(row[k][0].z), a0);
            a1 = __hfma2(vh[6],  u2h2(row[k][1].z), a1);
            a2 = __hfma2(vh[10], u2h2(row[k][2].z), a2);
            a3 = __hfma2(vh[14], u2h2(row[k][3].z), a3);
            a0 = __hfma2(vh[3],  u2h2(row[k][0].w), a0);
            a1 = __hfma2(vh[7],  u2h2(row[k][1].w), a1);
            a2 = __hfma2(vh[11], u2h2(row[k][2].w), a2);
            a3 = __hfma2(vh[15], u2h2(row[k][3].w), a3);
            float2 f0 = __half22float2(a0), f1 = __half22float2(a1);
            float2 f2 = __half22float2(a2), f3 = __half22float2(a3);
            float d = ((f0.x + f0.y) + (f1.x + f1.y)) + ((f2.x + f2.y) + (f3.x + f3.y));
            b[k] += d;
            float e = __expf(b[k] - Mprev);
            z += e;
            mloc = fmaxf(mloc, b[k]);
            __half2 eh = __half2half2(__float2half_rn(e));
            #pragma unroll
            for (int c = 0; c < 4; c++) {
                s_acc[c * 4 + 0] = __hfma2(eh, u2h2(row[k][c].x), s_acc[c * 4 + 0]);
                s_acc[c * 4 + 1] = __hfma2(eh, u2h2(row[k][c].y), s_acc[c * 4 + 1]);
                s_acc[c * 4 + 2] = __hfma2(eh, u2h2(row[k][c].z), s_acc[c * 4 + 2]);
                s_acc[c * 4 + 3] = __hfma2(eh, u2h2(row[k][c].w), s_acc[c * 4 + 3]);
            }
        }
    }
}

// ---------------------------------------------------------------------------
extern "C" void kernel_launch(void* const* d_in, const int* in_sizes, int n_in,
                              void* d_out, int out_size)
{
    const float* x = (const float*)d_in[0];
    const float* W = (const float*)d_in[1];
    if (n_in >= 2 && in_sizes[0] > in_sizes[1]) {
        x = (const float*)d_in[1];
        W = (const float*)d_in[0];
    }

    uhat_kernel<<<NIN, 256>>>(x, W);
    routing_kernel<<<B_ * J_, RT>>>((float*)d_out);

    (void)out_size;
}